// round 2
// baseline (speedup 1.0000x reference)
#include <cuda_runtime.h>
#include <math_constants.h>

// BackupBarrierCBF: 50-step braking rollout of ego+agent unicycles, then
// min-over-time oriented-box separation distance, squashed by 5*tanh(h/10).
//
// Structure exploited:
//  - turn control == 0  -> theta (slot 3) constant -> dynamics sincos hoisted
//  - NOTE: veh_veh_distance rotates by state slot 2 == VELOCITY (reference
//    passes [x,y,v] as the pose) -> sincos(v) recomputed every step
//  - extents constant   -> all distance thresholds precomputed
//  - dist.min(-1)       -> fully fused rollout+distance loop, no traj storage

#define N_T 50

__global__ __launch_bounds__(64)
void cbf_kernel(const float* __restrict__ data, float* __restrict__ out, int n)
{
    int i = blockIdx.x * blockDim.x + threadIdx.x;
    if (i >= n) return;

    const float* p = data + (size_t)i * 15;
    float xe  = p[0],  ye  = p[1],  ve = p[2],  the = p[3];
    float xa  = p[4],  ya  = p[5],  va = p[6],  tha = p[7];
    float ee0 = p[8],  ee1 = p[9];
    float ae0 = p[11], ae1 = p[12];
    float dt  = p[14];

    // dynamics heading (slot 3) is constant: hoist
    float se, ce, sa, ca;
    __sincosf(the, &se, &ce);
    __sincosf(tha, &sa, &ca);
    float dtce = dt * ce, dtse = dt * se;
    float dtca = dt * ca, dtsa = dt * sa;
    float m9dt = -9.0f * dt;                   // v += dt * (-9 * tanh(2v))

    float r_ag = 0.5f * sqrtf(ae0 * ae0 + ae1 * ae1);
    float r_eg = 0.5f * sqrtf(ee0 * ee0 + ee1 * ee1);
    float t1x = 0.5f * ee0 + r_ag, t1y = 0.5f * ee1 + r_ag;
    float t2x = 0.5f * ae0 + r_eg, t2y = 0.5f * ae1 + r_eg;

    float hmin = CUDART_INF_F;

#pragma unroll 5
    for (int t = 0; t < N_T; t++) {
        // --- controller + Euler step (u from current state; x uses current v) ---
        // tanh(2v) = (1 - e)/(1 + e), e = exp(-4v)   (accurate: feeds recursion)
        float ee = __expf(-4.0f * ve);
        float te = (1.0f - ee) * __fdividef(1.0f, 1.0f + ee);
        float ea = __expf(-4.0f * va);
        float ta = (1.0f - ea) * __fdividef(1.0f, 1.0f + ea);

        xe = fmaf(dtce, ve, xe);
        ye = fmaf(dtse, ve, ye);
        xa = fmaf(dtca, va, xa);
        ya = fmaf(dtsa, va, ya);
        ve = fmaf(m9dt, te, ve);
        va = fmaf(m9dt, ta, va);

        // --- oriented-box separation at post-step state ---
        // rotation angle = post-step VELOCITY (reference passes [x,y,v] as pose)
        float sve, cve, sva, cva;
        __sincosf(ve, &sve, &cve);
        __sincosf(va, &sva, &cva);

        float dx = xa - xe, dy = ya - ye;
        // rel1 = R(-ve)*d ; rel2 = R(-va)*(-d), sign absorbed by abs
        float r1x = fabsf(fmaf(cve, dx,  sve * dy)) - t1x;
        float r1y = fabsf(fmaf(cve, dy, -sve * dx)) - t1y;
        float r2x = fabsf(fmaf(cva, dx,  sva * dy)) - t2x;
        float r2y = fabsf(fmaf(sva, dx, -cva * dy)) - t2y;

        float d = fmaxf(fmaxf(r1x, r1y), fmaxf(r2x, r2y));
        hmin = fminf(hmin, d);
    }

    // (sigmoid(h/5) - 0.5) * 2 * 5 == 5 * tanh(h/10) ; accurate path, runs once
    out[i] = 5.0f * tanhf(hmin * 0.1f);
}

extern "C" void kernel_launch(void* const* d_in, const int* in_sizes, int n_in,
                              void* d_out, int out_size)
{
    const float* data = (const float*)d_in[0];
    float* out = (float*)d_out;
    int n = out_size;  // B*A elements; in_sizes[0] == n*15
    int threads = 64;
    int blocks = (n + threads - 1) / threads;
    cbf_kernel<<<blocks, threads>>>(data, out, n);
}